// round 14
// baseline (speedup 1.0000x reference)
#include <cuda_runtime.h>
#include <cstdint>

#define NNODES 8192
#define FEATD  1024
#define HDIM   512
#define GDIM   (5*HDIM)
#define NCTA   128
#define WPC    4                 // warps per CTA; warp w owns unit cta*4+w
#define NTHR   (WPC*32)
#define NVC    16                // value mailbox copies (8B {val,tag})
#define SENT   0xFFC0DEADu      // sentinel for g_C only (general-tree path)

// Scratch (static __device__ arrays: allocation-free per harness rules)
__device__ float g_xgb[(size_t)NNODES * GDIM];   // Wx·x + bx + bh   [N,5H]
__device__ float g_pxb[(size_t)NNODES * HDIM];   // Wpx·x + bpx      [N,H]
__device__ float g_C[(size_t)NNODES * HDIM];     // cell states      [N,H]
// Fused mailbox: [parity][copy][unit] = {h bits, tag = t+1}    (128KB)
__device__ __align__(128) uint2 g_mval[2][NVC][HDIM];
// DWORD tag pre-filter: [parity][copy][unit] = t+1             (64KB)
// 4-byte stores: no sub-word ECC RMW pathology (R10's bug).
__device__ __align__(128) unsigned g_tagd[2][NVC][HDIM];

__device__ __forceinline__ float sigm(float x) {
    return 1.0f / (1.0f + __expf(-x));
}
__device__ __forceinline__ float tanhfast(float x) {
    return 1.0f - 2.0f / (__expf(2.0f * x) + 1.0f);
}
__device__ __forceinline__ uint4 ld_volatile_u4(const void* p) {
    uint4 v;
    asm volatile("ld.volatile.global.v4.b32 {%0,%1,%2,%3}, [%4];"
                 : "=r"(v.x), "=r"(v.y), "=r"(v.z), "=r"(v.w) : "l"(p) : "memory");
    return v;
}
__device__ __forceinline__ float ld_volatile_f(const float* p) {
    float v;
    asm volatile("ld.volatile.global.f32 %0, [%1];" : "=f"(v) : "l"(p) : "memory");
    return v;
}
__device__ __forceinline__ void st_v2_u32(void* p, unsigned a, unsigned b) {
    asm volatile("st.global.v2.b32 [%0], {%1,%2};" :: "l"(p), "r"(a), "r"(b) : "memory");
}
__device__ __forceinline__ void st_u32(void* p, unsigned a) {
    asm volatile("st.global.b32 [%0], %1;" :: "l"(p), "r"(a) : "memory");
}
__device__ __forceinline__ float desent(float v) {   // g_C values only
    return (__float_as_uint(v) == SENT) ? __uint_as_float(SENT ^ 1u) : v;
}

// ---------------------------------------------------------------------------
// Per-launch reset: zero mailbox+tags (192KB) + sentinel-poison g_C (16MB).
// ---------------------------------------------------------------------------
#define MV_U4   (int)(sizeof(g_mval) / 16)       // 8192
#define TD_U4   (int)(sizeof(g_tagd) / 16)       // 4096
#define GC_F4   (NNODES * HDIM / 4)              // 1048576
__global__ void poison_kernel(float4* __restrict__ gc) {
    int i = blockIdx.x * blockDim.x + threadIdx.x;
    if (i < MV_U4)
        ((uint4*)g_mval)[i] = make_uint4(0u, 0u, 0u, 0u);
    int k = i - MV_U4;
    if (k >= 0 && k < TD_U4)
        ((uint4*)g_tagd)[k] = make_uint4(0u, 0u, 0u, 0u);
    int j = k - TD_U4;
    if (j >= 0 && j < GC_F4) {
        float f = __uint_as_float(SENT);
        gc[j] = make_float4(f, f, f, f);
    }
}

// ---------------------------------------------------------------------------
// Batched precompute GEMM:  C[M,N] = A[M,K] * B[N,K]^T + b1[N] (+ b2[N])
// 128x128x8 SMEM-tiled fp32, 256 threads, 8x8 per-thread tile.
// ---------------------------------------------------------------------------
__global__ __launch_bounds__(256) void sgemm_bt_bias(
    const float* __restrict__ A, const float* __restrict__ B,
    const float* __restrict__ b1, const float* __restrict__ b2,
    float* __restrict__ C, int M, int N, int K)
{
    const int BM = 128, BN = 128;
    __shared__ float As[8][BM + 4];
    __shared__ float Bs[8][BN + 4];

    const int tid = threadIdx.x;
    const int bxi = blockIdx.x, byi = blockIdx.y;
    const int loadRow = tid >> 1;
    const int loadCol = (tid & 1) << 2;

    const float* Ab = A + (size_t)byi * BM * K;
    const float* Bb = B + (size_t)bxi * BN * K;

    const int ty = tid >> 4;
    const int tx = tid & 15;

    float acc[8][8];
#pragma unroll
    for (int i = 0; i < 8; i++)
#pragma unroll
        for (int j = 0; j < 8; j++) acc[i][j] = 0.0f;

    for (int k0 = 0; k0 < K; k0 += 8) {
        float4 av = *(const float4*)(Ab + (size_t)loadRow * K + k0 + loadCol);
        float4 bv = *(const float4*)(Bb + (size_t)loadRow * K + k0 + loadCol);
        As[loadCol + 0][loadRow] = av.x;
        As[loadCol + 1][loadRow] = av.y;
        As[loadCol + 2][loadRow] = av.z;
        As[loadCol + 3][loadRow] = av.w;
        Bs[loadCol + 0][loadRow] = bv.x;
        Bs[loadCol + 1][loadRow] = bv.y;
        Bs[loadCol + 2][loadRow] = bv.z;
        Bs[loadCol + 3][loadRow] = bv.w;
        __syncthreads();

#pragma unroll
        for (int k = 0; k < 8; k++) {
            float ar[8], br[8];
#pragma unroll
            for (int i = 0; i < 8; i++) ar[i] = As[k][ty * 8 + i];
#pragma unroll
            for (int j = 0; j < 8; j++) br[j] = Bs[k][tx * 8 + j];
#pragma unroll
            for (int i = 0; i < 8; i++)
#pragma unroll
                for (int j = 0; j < 8; j++)
                    acc[i][j] = fmaf(ar[i], br[j], acc[i][j]);
        }
        __syncthreads();
    }

#pragma unroll
    for (int i = 0; i < 8; i++) {
        int m = byi * BM + ty * 8 + i;
        int nbase = bxi * BN + tx * 8;
        float v[8];
#pragma unroll
        for (int j = 0; j < 8; j++) {
            v[j] = acc[i][j] + b1[nbase + j];
            if (b2) v[j] += b2[nbase + j];
        }
        float4* out = (float4*)(C + (size_t)m * N + nbase);
        out[0] = make_float4(v[0], v[1], v[2], v[3]);
        out[1] = make_float4(v[4], v[5], v[6], v[7]);
    }
}

// ---------------------------------------------------------------------------
// Persistent serial recurrence. 128 CTAs x 128 threads; warp w owns unit
// cta*4+w (80 weight regs). Detection: (1) poll the DWORD tag array — one
// uint4/lane covers all 128 tags of the warp's quarter (512B/warp/iter,
// ~4x less poll traffic -> below the LTS cap), (2) one-shot load of fused
// {value,tag32} pairs with inline verify respin (pre-filter is advisory;
// the embedded tag32 is the sole source of truth — no fences needed).
// ---------------------------------------------------------------------------
__global__ __launch_bounds__(NTHR, 1) void treelstm_seq_kernel(
    const float* __restrict__ Wh, const int* __restrict__ parents,
    float* __restrict__ Hout)
{
    __shared__ float s_h[HDIM];      // assembled h[parent] (2KB)
    __shared__ int   s_par[NNODES];  // parents table (32KB)

    const int cta  = blockIdx.x;
    const int w    = threadIdx.x >> 5;
    const int lane = threadIdx.x & 31;
    const int unit = cta * WPC + w;
    const int cval = cta & (NVC - 1);    // this CTA's mailbox/tag copy
    const int qu   = 128 * w;            // this warp's unit quarter

    for (int i = threadIdx.x; i < NNODES; i += NTHR) s_par[i] = parents[i];

    // Pin this unit's 5 Wh rows in registers: lane covers k = 4*lane + 128*c.
    float4 wv[5][4];
#pragma unroll
    for (int g = 0; g < 5; g++) {
        const float* wrow = Wh + (size_t)(g * HDIM + unit) * HDIM + 4 * lane;
#pragma unroll
        for (int c = 0; c < 4; c++)
            wv[g][c] = *(const float4*)(wrow + 128 * c);
    }

    // Node-0 static terms (lane-uniform broadcast loads, all lanes)
    float xg[5], px;
#pragma unroll
    for (int g = 0; g < 5; g++) xg[g] = g_xgb[(size_t)(g * HDIM + unit)];
    px = g_pxb[unit];

    __syncthreads();                 // s_par ready
    float c_last = 0.0f;
    int p = s_par[0];

    for (int t = 0; t < NNODES; t++) {
        const int p_next = (t + 1 < NNODES) ? s_par[t + 1] : 0;

        float4 h0, h1, h2, h3;
        if (p >= 0) {
            const unsigned e = (unsigned)(p + 1);
            // --- level 1: dword-tag poll; one uint4/lane = 4 tags, warp
            //     covers all 128 tags of its quarter (512B per iteration) ---
            {
                const unsigned* tp = &g_tagd[p & 1][cval][qu + 4 * lane];
                for (;;) {
                    uint4 tv = ld_volatile_u4(tp);
                    bool ok = (tv.x == e) & (tv.y == e) &
                              (tv.z == e) & (tv.w == e);
                    if (__all_sync(0xffffffffu, ok)) break;
                }
            }
            // --- level 2: one-shot value load + inline tag verify respin ---
            // lane covers units {2l, 2l+1, 64+2l, 64+2l+1} of the quarter
            {
                const uint2* mp = &g_mval[p & 1][cval][qu + 2 * lane];
                uint4 v0, v1;
                for (;;) {
                    v0 = ld_volatile_u4(mp);
                    v1 = ld_volatile_u4(mp + 64);
                    bool ok = (v0.y == e) & (v0.w == e) &
                              (v1.y == e) & (v1.w == e);
                    if (__all_sync(0xffffffffu, ok)) break;
                }
                *(float2*)&s_h[qu + 2 * lane] =
                    make_float2(__uint_as_float(v0.x), __uint_as_float(v0.z));
                *(float2*)&s_h[qu + 64 + 2 * lane] =
                    make_float2(__uint_as_float(v1.x), __uint_as_float(v1.z));
            }
            __syncthreads();                   // s_h fully assembled
            h0 = *(const float4*)&s_h[4 * lane +   0];
            h1 = *(const float4*)&s_h[4 * lane + 128];
            h2 = *(const float4*)&s_h[4 * lane + 256];
            h3 = *(const float4*)&s_h[4 * lane + 384];
        } else {
            h0 = h1 = h2 = h3 = make_float4(0.f, 0.f, 0.f, 0.f);
        }

        // --- 5 dot products (this unit's i,o,f,u,r rows) ---
        float acc[5];
#pragma unroll
        for (int g = 0; g < 5; g++) {
            float a0 = fmaf(wv[g][0].x, h0.x, fmaf(wv[g][0].y, h0.y,
                       fmaf(wv[g][0].z, h0.z, wv[g][0].w * h0.w)));
            float a1 = fmaf(wv[g][1].x, h1.x, fmaf(wv[g][1].y, h1.y,
                       fmaf(wv[g][1].z, h1.z, wv[g][1].w * h1.w)));
            float a2 = fmaf(wv[g][2].x, h2.x, fmaf(wv[g][2].y, h2.y,
                       fmaf(wv[g][2].z, h2.z, wv[g][2].w * h2.w)));
            float a3 = fmaf(wv[g][3].x, h3.x, fmaf(wv[g][3].y, h3.y,
                       fmaf(wv[g][3].z, h3.z, wv[g][3].w * h3.w)));
            acc[g] = (a0 + a1) + (a2 + a3);
        }

        // --- fused 5-way butterfly reduce: ALL lanes end with the sums ---
#pragma unroll
        for (int off = 16; off; off >>= 1) {
#pragma unroll
            for (int g = 0; g < 5; g++)
                acc[g] += __shfl_xor_sync(0xffffffffu, acc[g], off);
        }

        // --- gate math on ALL lanes (redundant; enables wide fan-out) ---
        float cpar = 0.0f;
        if (p >= 0) {
            if (p == t - 1) {
                cpar = c_last;                           // chain fast path
            } else {
                const float* cp = &g_C[(size_t)p * HDIM + unit];
                do { cpar = ld_volatile_f(cp); }         // general tree
                while (__float_as_uint(cpar) == SENT);
            }
        }
        float iv = sigm(acc[0] + xg[0]);
        float ov = sigm(acc[1] + xg[1]);
        float fv = sigm(acc[2] + xg[2]);
        float uv = tanhfast(acc[3] + xg[3]);
        float rv = sigm(acc[4] + xg[4]);
        float c  = desent(fmaf(fv, cpar, iv * uv));
        float hh = ov * tanhfast(c);
        float hf = rv * hh + (1.0f - rv) * px;
        c_last = c;

        // --- publish: values (lanes 16..31), then dword tags (lanes 0..15) ---
        const unsigned tagp = (unsigned)(t + 1);
        if (lane >= 16)                                     // 16 value copies
            st_v2_u32(&g_mval[t & 1][lane - 16][unit],
                      __float_as_uint(hf), tagp);
        if (lane < NVC)                                     // 16 dword tags
            st_u32(&g_tagd[t & 1][lane][unit], tagp);
        if (lane == 0) Hout[(size_t)t * HDIM + unit] = hf;  // final output
        if (lane == 1) g_C[(size_t)t * HDIM + unit]  = c;   // general-tree state

        // --- prefetch next node's static terms (broadcast, off-path) ---
        if (t + 1 < NNODES) {
#pragma unroll
            for (int g = 0; g < 5; g++)
                xg[g] = g_xgb[(size_t)(t + 1) * GDIM + g * HDIM + unit];
            px = g_pxb[(size_t)(t + 1) * HDIM + unit];
        }

        // s_h reuse is globally gated on the chain; bar only for non-chain t+1.
        if (t + 1 < NNODES && p_next != t) __syncthreads();

        p = p_next;
    }
}

extern "C" void kernel_launch(void* const* d_in, const int* in_sizes, int n_in,
                              void* d_out, int out_size) {
    const float* features = (const float*)d_in[0];
    const int*   parents  = (const int*)d_in[1];
    const float* Wpx      = (const float*)d_in[2];
    const float* bpx      = (const float*)d_in[3];
    const float* Wx       = (const float*)d_in[4];
    const float* bx       = (const float*)d_in[5];
    const float* Wh       = (const float*)d_in[6];
    const float* bh       = (const float*)d_in[7];
    float* Hout = (float*)d_out;

    float* d_pxb = nullptr;
    float* d_xgb = nullptr;
    float* d_C   = nullptr;
    cudaGetSymbolAddress((void**)&d_pxb, g_pxb);
    cudaGetSymbolAddress((void**)&d_xgb, g_xgb);
    cudaGetSymbolAddress((void**)&d_C,   g_C);

    // 1) reset mailbox+tags, sentinel-poison g_C (replay-safe)
    poison_kernel<<<(MV_U4 + TD_U4 + GC_F4 + 255) / 256, 256>>>((float4*)d_C);

    // 2) batched x-side projections
    dim3 gpx(HDIM / 128, NNODES / 128);
    sgemm_bt_bias<<<gpx, 256>>>(features, Wpx, bpx, nullptr, d_pxb,
                                NNODES, HDIM, FEATD);
    dim3 gxg(GDIM / 128, NNODES / 128);
    sgemm_bt_bias<<<gxg, 256>>>(features, Wx, bx, bh, d_xgb,
                                NNODES, GDIM, FEATD);

    // 3) serial recurrence (dword-tag prefilter + fused mailbox, 128 CTAs)
    treelstm_seq_kernel<<<NCTA, NTHR>>>(Wh, parents, Hout);
}

// round 15
// speedup vs baseline: 1.4299x; 1.4299x over previous
#include <cuda_runtime.h>
#include <cstdint>

#define NNODES 8192
#define FEATD  1024
#define HDIM   512
#define GDIM   (5*HDIM)
#define NCTA   128
#define WPC    4                 // warps per CTA; warp w owns unit cta*4+w
#define NTHR   (WPC*32)
#define NVC    16                // value mailbox copies (8B {val,tag})
#define SENT   0xFFC0DEADu      // sentinel for g_C only (general-tree path)

// Scratch (static __device__ arrays: allocation-free per harness rules)
__device__ float g_xgb[(size_t)NNODES * GDIM];   // Wx·x + bx + bh   [N,5H]
__device__ float g_pxb[(size_t)NNODES * HDIM];   // Wpx·x + bpx      [N,H]
__device__ float g_C[(size_t)NNODES * HDIM];     // cell states      [N,H]
// Fused mailbox: [parity][copy][unit] = {h bits, tag = t+1}    (128KB)
__device__ __align__(128) uint2 g_mval[2][NVC][HDIM];

__device__ __forceinline__ float sigm(float x) {
    return 1.0f / (1.0f + __expf(-x));
}
__device__ __forceinline__ float tanhfast(float x) {
    return 1.0f - 2.0f / (__expf(2.0f * x) + 1.0f);
}
__device__ __forceinline__ uint4 ld_volatile_u4(const void* p) {
    uint4 v;
    asm volatile("ld.volatile.global.v4.b32 {%0,%1,%2,%3}, [%4];"
                 : "=r"(v.x), "=r"(v.y), "=r"(v.z), "=r"(v.w) : "l"(p) : "memory");
    return v;
}
__device__ __forceinline__ float ld_volatile_f(const float* p) {
    float v;
    asm volatile("ld.volatile.global.f32 %0, [%1];" : "=f"(v) : "l"(p) : "memory");
    return v;
}
__device__ __forceinline__ void st_v2_u32(void* p, unsigned a, unsigned b) {
    asm volatile("st.global.v2.b32 [%0], {%1,%2};" :: "l"(p), "r"(a), "r"(b) : "memory");
}
__device__ __forceinline__ float desent(float v) {   // g_C values only
    return (__float_as_uint(v) == SENT) ? __uint_as_float(SENT ^ 1u) : v;
}

// ---------------------------------------------------------------------------
// Per-launch reset: zero mailbox (128KB) + sentinel-poison g_C (16MB).
// ---------------------------------------------------------------------------
#define MV_U4   (int)(sizeof(g_mval) / 16)       // 8192
#define GC_F4   (NNODES * HDIM / 4)              // 1048576
__global__ void poison_kernel(float4* __restrict__ gc) {
    int i = blockIdx.x * blockDim.x + threadIdx.x;
    if (i < MV_U4)
        ((uint4*)g_mval)[i] = make_uint4(0u, 0u, 0u, 0u);
    int j = i - MV_U4;
    if (j >= 0 && j < GC_F4) {
        float f = __uint_as_float(SENT);
        gc[j] = make_float4(f, f, f, f);
    }
}

// ---------------------------------------------------------------------------
// Batched precompute GEMM:  C[M,N] = A[M,K] * B[N,K]^T + b1[N] (+ b2[N])
// 128x128x8 SMEM-tiled fp32, 256 threads, 8x8 per-thread tile.
// ---------------------------------------------------------------------------
__global__ __launch_bounds__(256) void sgemm_bt_bias(
    const float* __restrict__ A, const float* __restrict__ B,
    const float* __restrict__ b1, const float* __restrict__ b2,
    float* __restrict__ C, int M, int N, int K)
{
    const int BM = 128, BN = 128;
    __shared__ float As[8][BM + 4];
    __shared__ float Bs[8][BN + 4];

    const int tid = threadIdx.x;
    const int bxi = blockIdx.x, byi = blockIdx.y;
    const int loadRow = tid >> 1;
    const int loadCol = (tid & 1) << 2;

    const float* Ab = A + (size_t)byi * BM * K;
    const float* Bb = B + (size_t)bxi * BN * K;

    const int ty = tid >> 4;
    const int tx = tid & 15;

    float acc[8][8];
#pragma unroll
    for (int i = 0; i < 8; i++)
#pragma unroll
        for (int j = 0; j < 8; j++) acc[i][j] = 0.0f;

    for (int k0 = 0; k0 < K; k0 += 8) {
        float4 av = *(const float4*)(Ab + (size_t)loadRow * K + k0 + loadCol);
        float4 bv = *(const float4*)(Bb + (size_t)loadRow * K + k0 + loadCol);
        As[loadCol + 0][loadRow] = av.x;
        As[loadCol + 1][loadRow] = av.y;
        As[loadCol + 2][loadRow] = av.z;
        As[loadCol + 3][loadRow] = av.w;
        Bs[loadCol + 0][loadRow] = bv.x;
        Bs[loadCol + 1][loadRow] = bv.y;
        Bs[loadCol + 2][loadRow] = bv.z;
        Bs[loadCol + 3][loadRow] = bv.w;
        __syncthreads();

#pragma unroll
        for (int k = 0; k < 8; k++) {
            float ar[8], br[8];
#pragma unroll
            for (int i = 0; i < 8; i++) ar[i] = As[k][ty * 8 + i];
#pragma unroll
            for (int j = 0; j < 8; j++) br[j] = Bs[k][tx * 8 + j];
#pragma unroll
            for (int i = 0; i < 8; i++)
#pragma unroll
                for (int j = 0; j < 8; j++)
                    acc[i][j] = fmaf(ar[i], br[j], acc[i][j]);
        }
        __syncthreads();
    }

#pragma unroll
    for (int i = 0; i < 8; i++) {
        int m = byi * BM + ty * 8 + i;
        int nbase = bxi * BN + tx * 8;
        float v[8];
#pragma unroll
        for (int j = 0; j < 8; j++) {
            v[j] = acc[i][j] + b1[nbase + j];
            if (b2) v[j] += b2[nbase + j];
        }
        float4* out = (float4*)(C + (size_t)m * N + nbase);
        out[0] = make_float4(v[0], v[1], v[2], v[3]);
        out[1] = make_float4(v[4], v[5], v[6], v[7]);
    }
}

// ---------------------------------------------------------------------------
// Persistent serial recurrence (R8 structure + cross-step poll prefetch).
// 128 CTAs x 128 threads; warp w owns unit cta*4+w (80 weight regs).
// Single-level 16-copy fused {value,tag32} mailbox; inline tag verify is the
// sole source of truth (no fences). NEW: right after publishing step t, each
// warp issues the FIRST sample of step t+1's poll; it flies during the gate
// math / prefetch / loop overhead, so the verify loop usually starts with
// data already in hand — removing the sampling-quantization latency and
// halving steady-state poll traffic vs the 2-deep rotation.
// ---------------------------------------------------------------------------
__global__ __launch_bounds__(NTHR, 1) void treelstm_seq_kernel(
    const float* __restrict__ Wh, const int* __restrict__ parents,
    float* __restrict__ Hout)
{
    __shared__ float s_h[HDIM];      // assembled h[parent] (2KB)
    __shared__ int   s_par[NNODES];  // parents table (32KB)

    const int cta  = blockIdx.x;
    const int w    = threadIdx.x >> 5;
    const int lane = threadIdx.x & 31;
    const int unit = cta * WPC + w;
    const int cval = cta & (NVC - 1);    // this CTA's mailbox copy (8 readers)
    const int qu   = 128 * w;            // this warp's unit quarter

    for (int i = threadIdx.x; i < NNODES; i += NTHR) s_par[i] = parents[i];

    // Pin this unit's 5 Wh rows in registers: lane covers k = 4*lane + 128*c.
    float4 wv[5][4];
#pragma unroll
    for (int g = 0; g < 5; g++) {
        const float* wrow = Wh + (size_t)(g * HDIM + unit) * HDIM + 4 * lane;
#pragma unroll
        for (int c = 0; c < 4; c++)
            wv[g][c] = *(const float4*)(wrow + 128 * c);
    }

    // Node-0 static terms (lane-uniform broadcast loads, all lanes)
    float xg[5], px;
#pragma unroll
    for (int g = 0; g < 5; g++) xg[g] = g_xgb[(size_t)(g * HDIM + unit)];
    px = g_pxb[unit];

    __syncthreads();                 // s_par ready
    float c_last = 0.0f;
    int p = s_par[0];

    uint4 pv0, pv1;                  // cross-step prefetched poll sample
    bool  have_pf = false;

    for (int t = 0; t < NNODES; t++) {
        const int p_next = (t + 1 < NNODES) ? s_par[t + 1] : -1;

        float4 h0, h1, h2, h3;
        if (p >= 0) {
            const unsigned e = (unsigned)(p + 1);
            const uint2* mp = &g_mval[p & 1][cval][qu + 2 * lane];
            // --- fused detect+load, seeded by the cross-step prefetch ---
            {
                uint4 v0, v1;
                if (have_pf) { v0 = pv0; v1 = pv1; }
                else         { v0 = ld_volatile_u4(mp);
                               v1 = ld_volatile_u4(mp + 64); }
                for (;;) {
                    bool ok = (v0.y == e) & (v0.w == e) &
                              (v1.y == e) & (v1.w == e);
                    if (__all_sync(0xffffffffu, ok)) break;
                    v0 = ld_volatile_u4(mp);
                    v1 = ld_volatile_u4(mp + 64);
                }
                *(float2*)&s_h[qu + 2 * lane] =
                    make_float2(__uint_as_float(v0.x), __uint_as_float(v0.z));
                *(float2*)&s_h[qu + 64 + 2 * lane] =
                    make_float2(__uint_as_float(v1.x), __uint_as_float(v1.z));
            }
            __syncthreads();                   // s_h fully assembled
            h0 = *(const float4*)&s_h[4 * lane +   0];
            h1 = *(const float4*)&s_h[4 * lane + 128];
            h2 = *(const float4*)&s_h[4 * lane + 256];
            h3 = *(const float4*)&s_h[4 * lane + 384];
        } else {
            h0 = h1 = h2 = h3 = make_float4(0.f, 0.f, 0.f, 0.f);
        }

        // --- 5 dot products (this unit's i,o,f,u,r rows) ---
        float acc[5];
#pragma unroll
        for (int g = 0; g < 5; g++) {
            float a0 = fmaf(wv[g][0].x, h0.x, fmaf(wv[g][0].y, h0.y,
                       fmaf(wv[g][0].z, h0.z, wv[g][0].w * h0.w)));
            float a1 = fmaf(wv[g][1].x, h1.x, fmaf(wv[g][1].y, h1.y,
                       fmaf(wv[g][1].z, h1.z, wv[g][1].w * h1.w)));
            float a2 = fmaf(wv[g][2].x, h2.x, fmaf(wv[g][2].y, h2.y,
                       fmaf(wv[g][2].z, h2.z, wv[g][2].w * h2.w)));
            float a3 = fmaf(wv[g][3].x, h3.x, fmaf(wv[g][3].y, h3.y,
                       fmaf(wv[g][3].z, h3.z, wv[g][3].w * h3.w)));
            acc[g] = (a0 + a1) + (a2 + a3);
        }

        // --- fused 5-way butterfly reduce: ALL lanes end with the sums ---
#pragma unroll
        for (int off = 16; off; off >>= 1) {
#pragma unroll
            for (int g = 0; g < 5; g++)
                acc[g] += __shfl_xor_sync(0xffffffffu, acc[g], off);
        }

        // --- gate math on ALL lanes (redundant; enables wide fan-out) ---
        float cpar = 0.0f;
        if (p >= 0) {
            if (p == t - 1) {
                cpar = c_last;                           // chain fast path
            } else {
                const float* cp = &g_C[(size_t)p * HDIM + unit];
                do { cpar = ld_volatile_f(cp); }         // general tree
                while (__float_as_uint(cpar) == SENT);
            }
        }
        float iv = sigm(acc[0] + xg[0]);
        float ov = sigm(acc[1] + xg[1]);
        float fv = sigm(acc[2] + xg[2]);
        float uv = tanhfast(acc[3] + xg[3]);
        float rv = sigm(acc[4] + xg[4]);
        float c  = desent(fmaf(fv, cpar, iv * uv));
        float hh = ov * tanhfast(c);
        float hf = rv * hh + (1.0f - rv) * px;
        c_last = c;

        // --- publish: lanes 16..31 fan {hf, t+1} out to the 16 copies ---
        const unsigned tagp = (unsigned)(t + 1);
        if (lane >= 16)
            st_v2_u32(&g_mval[t & 1][lane - 16][unit],
                      __float_as_uint(hf), tagp);
        if (lane == 0) Hout[(size_t)t * HDIM + unit] = hf;  // final output
        if (lane == 1) g_C[(size_t)t * HDIM + unit]  = c;   // general-tree state

        // --- cross-step poll prefetch: first sample of step t+1's detect,
        //     issued NOW so it flies under the remaining loop overhead ---
        if (p_next >= 0) {
            const uint2* mpn = &g_mval[p_next & 1][cval][qu + 2 * lane];
            pv0 = ld_volatile_u4(mpn);
            pv1 = ld_volatile_u4(mpn + 64);
            have_pf = true;
        } else {
            have_pf = false;
        }

        // --- prefetch next node's static terms (broadcast, off-path) ---
        if (t + 1 < NNODES) {
#pragma unroll
            for (int g = 0; g < 5; g++)
                xg[g] = g_xgb[(size_t)(t + 1) * GDIM + g * HDIM + unit];
            px = g_pxb[(size_t)(t + 1) * HDIM + unit];
        }

        // s_h reuse is globally gated on the chain; bar only for non-chain t+1.
        if (t + 1 < NNODES && p_next != t) __syncthreads();

        p = p_next;
    }
}

extern "C" void kernel_launch(void* const* d_in, const int* in_sizes, int n_in,
                              void* d_out, int out_size) {
    const float* features = (const float*)d_in[0];
    const int*   parents  = (const int*)d_in[1];
    const float* Wpx      = (const float*)d_in[2];
    const float* bpx      = (const float*)d_in[3];
    const float* Wx       = (const float*)d_in[4];
    const float* bx       = (const float*)d_in[5];
    const float* Wh       = (const float*)d_in[6];
    const float* bh       = (const float*)d_in[7];
    float* Hout = (float*)d_out;

    float* d_pxb = nullptr;
    float* d_xgb = nullptr;
    float* d_C   = nullptr;
    cudaGetSymbolAddress((void**)&d_pxb, g_pxb);
    cudaGetSymbolAddress((void**)&d_xgb, g_xgb);
    cudaGetSymbolAddress((void**)&d_C,   g_C);

    // 1) reset mailbox, sentinel-poison g_C (replay-safe)
    poison_kernel<<<(MV_U4 + GC_F4 + 255) / 256, 256>>>((float4*)d_C);

    // 2) batched x-side projections
    dim3 gpx(HDIM / 128, NNODES / 128);
    sgemm_bt_bias<<<gpx, 256>>>(features, Wpx, bpx, nullptr, d_pxb,
                                NNODES, HDIM, FEATD);
    dim3 gxg(GDIM / 128, NNODES / 128);
    sgemm_bt_bias<<<gxg, 256>>>(features, Wx, bx, bh, d_xgb,
                                NNODES, GDIM, FEATD);

    // 3) serial recurrence (prefetch-seeded tagged dataflow, 128 CTAs)
    treelstm_seq_kernel<<<NCTA, NTHR>>>(Wh, parents, Hout);
}